// round 13
// baseline (speedup 1.0000x reference)
#include <cuda_runtime.h>
#include <cuda_bf16.h>
#include <cstdint>

// Batched FWHT, N = 4096, scale 1/64. Persistent CTAs, cp.async double-buffered
// row pipeline: row i+1 streams into smem buf B while row i computes out of A.
//
// Per-row compute (identical numerics to R11, rel_err ~1.3e-7):
//   read : e = t | k<<8 from smem (LDS.32 x16, conflict-free)
//   P1 H16 on e[8:12]; ex1 swz1 = e ^ ((e>>4)&31)   (STS/LDS CF)
//   P2 H16 on e[0:4] ; ex2 swz2 = e ^ ((e>>5)&15) ^ (e8<<4) (STS/LDS CF)
//   P3 H16 on e[4:8] ; store e = (t&15)|r<<4|(t>>4)<<8 (2 full 64B runs/instr)

#define FWHT_N  4096
#define THREADS 256
#define GRID    1024        // persistent CTAs; 8192 rows -> 8 rows/CTA

__device__ __forceinline__ void cpasync16(unsigned int saddr, const void* gaddr) {
    asm volatile("cp.async.cg.shared.global [%0], [%1], 16;"
                 :: "r"(saddr), "l"(gaddr));
}
__device__ __forceinline__ void cp_commit() {
    asm volatile("cp.async.commit_group;");
}
__device__ __forceinline__ void cp_wait0() {
    asm volatile("cp.async.wait_group 0;");
}

__device__ __forceinline__ void h16(float v[16]) {
#pragma unroll
    for (int st = 1; st < 16; st <<= 1)
#pragma unroll
        for (int i = 0; i < 16; i++)
            if ((i & st) == 0) {
                float a = v[i], b = v[i | st];
                v[i]      = a + b;
                v[i | st] = a - b;
            }
}

__global__ __launch_bounds__(THREADS, 7) void fwht4096_kernel(
    const float* __restrict__ x, float* __restrict__ y, int rows)
{
    __shared__ float buf[2][FWHT_N];

    const int t = threadIdx.x;
    const int stride = gridDim.x;

    const unsigned int sb0 = (unsigned int)__cvta_generic_to_shared(&buf[0][0]);
    const unsigned int sb1 = (unsigned int)__cvta_generic_to_shared(&buf[1][0]);

    // Hoisted swizzle bases (t-only parts), identical to R11.
    const int b1s = t ^ ((t >> 4) & 15);                                // ex1 store
    const int b1l = (t << 4) ^ (t & 31);                                // ex1 load
    const int b2s = (t << 4) ^ ((t >> 1) & 15) ^ (((t >> 4) & 1) << 4); // ex2 store
    const int b2l = ((t & 15) | ((t >> 4) << 8))
                  ^ (((t >> 4) & 1) << 3) ^ (((t >> 4) & 1) << 4);      // ex2 load

    int row = blockIdx.x;

    // ---- Prologue: prefetch first row into buf[0] ----
    if (row < rows) {
        const char* g = (const char*)(x + (size_t)row * FWHT_N) + t * 16;
        const unsigned int d = sb0 + t * 16;
#pragma unroll
        for (int q = 0; q < 4; q++)
            cpasync16(d + q * 4096, g + q * 4096);
    }
    cp_commit();

    int cur = 0;
    for (; row < rows; row += stride) {
        // Land current row's data; fence the other buffer for re-use.
        cp_wait0();
        __syncthreads();

        const unsigned int snxt = cur ? sb0 : sb1;
        float* const sc = cur ? buf[1] : buf[0];

        // ---- Kick prefetch of next row into the other buffer ----
        const int nxt = row + stride;
        if (nxt < rows) {
            const char* g = (const char*)(x + (size_t)nxt * FWHT_N) + t * 16;
            const unsigned int d = snxt + t * 16;
#pragma unroll
            for (int q = 0; q < 4; q++)
                cpasync16(d + q * 4096, g + q * 4096);
        }
        cp_commit();

        float v[16];

        // ---- Read: e = t | k<<8 (conflict-free LDS) ----
#pragma unroll
        for (int k = 0; k < 16; k++)
            v[k] = sc[t | (k << 8)];

        // ---- P1: H16 on e[8:12] ----
        h16(v);
        __syncthreads();                 // all reads of sc done before in-place store

        // ---- Exchange 1 store (swz1, CF) ----
#pragma unroll
        for (int k = 0; k < 16; k++)
            sc[b1s ^ (k << 8) ^ ((k & 1) << 4)] = v[k];
        __syncthreads();

        // ---- Exchange 1 load (CF) ----
#pragma unroll
        for (int j = 0; j < 16; j++)
            v[j] = sc[b1l ^ j];

        // ---- P2: H16 on e[0:4] ----
        h16(v);
        __syncthreads();

        // ---- Exchange 2 store (swz2, CF) ----
#pragma unroll
        for (int j = 0; j < 16; j++)
            sc[b2s ^ j] = v[j];
        __syncthreads();

        // ---- Exchange 2 load (CF) ----
#pragma unroll
        for (int r = 0; r < 16; r++)
            v[r] = sc[b2l ^ (r << 4) ^ ((r >> 1) & 7)];

        // ---- P3: H16 on e[4:8] ----
        h16(v);

        // ---- Store: e = (t&15) | r<<4 | (t>>4)<<8, scale 1/64 ----
        {
            const float c = 1.0f / 64.0f;
            float* yr = y + (size_t)row * FWHT_N + (t & 15) + ((t >> 4) << 8);
#pragma unroll
            for (int r = 0; r < 16; r++)
                yr[r << 4] = v[r] * c;
        }

        cur ^= 1;
    }
}

extern "C" void kernel_launch(void* const* d_in, const int* in_sizes, int n_in,
                              void* d_out, int out_size) {
    const float* x = (const float*)d_in[0];
    float* y = (float*)d_out;
    const int rows = in_sizes[0] / FWHT_N;   // 8192
    const int grid = (rows < GRID) ? rows : GRID;
    fwht4096_kernel<<<grid, THREADS>>>(x, y, rows);
}

// round 14
// speedup vs baseline: 1.0693x; 1.0693x over previous
#include <cuda_runtime.h>
#include <cuda_bf16.h>
#include <cstdint>

// Batched FWHT, N = 4096, scale 1/64. Persistent CTAs (exactly one resident
// wave: 148 SMs x 6 CTAs = 888), cp.async double-buffered row pipeline:
// row i+1 streams into smem buf B while row i computes out of A.
//
// Per-row compute (validated numerics, rel_err ~1.3e-7):
//   read : e = t | k<<8 from smem (LDS.32 x16, conflict-free)
//   P1 H16 on e[8:12]; ex1 swz1 = e ^ ((e>>4)&31)   (STS/LDS CF)
//   P2 H16 on e[0:4] ; ex2 swz2 = e ^ ((e>>5)&15) ^ (e8<<4) (STS/LDS CF)
//   P3 H16 on e[4:8] ; store e = (t&15)|r<<4|(t>>4)<<8 via st.global.cs

#define FWHT_N  4096
#define THREADS 256
#define GRID    888         // 148 SMs x 6 CTAs/SM (32KB smem/CTA): ONE wave

__device__ __forceinline__ void cpasync16(unsigned int saddr, const void* gaddr) {
    asm volatile("cp.async.cg.shared.global [%0], [%1], 16;"
                 :: "r"(saddr), "l"(gaddr));
}
__device__ __forceinline__ void cp_commit() {
    asm volatile("cp.async.commit_group;");
}
__device__ __forceinline__ void cp_wait0() {
    asm volatile("cp.async.wait_group 0;");
}

__device__ __forceinline__ void h16(float v[16]) {
#pragma unroll
    for (int st = 1; st < 16; st <<= 1)
#pragma unroll
        for (int i = 0; i < 16; i++)
            if ((i & st) == 0) {
                float a = v[i], b = v[i | st];
                v[i]      = a + b;
                v[i | st] = a - b;
            }
}

__global__ __launch_bounds__(THREADS, 6) void fwht4096_kernel(
    const float* __restrict__ x, float* __restrict__ y, int rows)
{
    __shared__ float buf[2][FWHT_N];

    const int t = threadIdx.x;
    const int stride = gridDim.x;

    const unsigned int sb0 = (unsigned int)__cvta_generic_to_shared(&buf[0][0]);
    const unsigned int sb1 = (unsigned int)__cvta_generic_to_shared(&buf[1][0]);

    // Hoisted swizzle bases (t-only parts).
    const int b1s = t ^ ((t >> 4) & 15);                                // ex1 store
    const int b1l = (t << 4) ^ (t & 31);                                // ex1 load
    const int b2s = (t << 4) ^ ((t >> 1) & 15) ^ (((t >> 4) & 1) << 4); // ex2 store
    const int b2l = ((t & 15) | ((t >> 4) << 8))
                  ^ (((t >> 4) & 1) << 3) ^ (((t >> 4) & 1) << 4);      // ex2 load

    int row = blockIdx.x;

    // ---- Prologue: prefetch first row into buf[0] ----
    if (row < rows) {
        const char* g = (const char*)(x + (size_t)row * FWHT_N) + t * 16;
        const unsigned int d = sb0 + t * 16;
#pragma unroll
        for (int q = 0; q < 4; q++)
            cpasync16(d + q * 4096, g + q * 4096);
    }
    cp_commit();

    int cur = 0;
    for (; row < rows; row += stride) {
        // Land current row's data; fence the other buffer for re-use.
        cp_wait0();
        __syncthreads();

        const unsigned int snxt = cur ? sb0 : sb1;
        float* const sc = cur ? buf[1] : buf[0];

        // ---- Kick prefetch of next row into the other buffer ----
        const int nxt = row + stride;
        if (nxt < rows) {
            const char* g = (const char*)(x + (size_t)nxt * FWHT_N) + t * 16;
            const unsigned int d = snxt + t * 16;
#pragma unroll
            for (int q = 0; q < 4; q++)
                cpasync16(d + q * 4096, g + q * 4096);
        }
        cp_commit();

        float v[16];

        // ---- Read: e = t | k<<8 (conflict-free LDS) ----
#pragma unroll
        for (int k = 0; k < 16; k++)
            v[k] = sc[t | (k << 8)];

        // ---- P1: H16 on e[8:12] ----
        h16(v);
        __syncthreads();                 // all reads of sc done before in-place store

        // ---- Exchange 1 store (swz1, CF) ----
#pragma unroll
        for (int k = 0; k < 16; k++)
            sc[b1s ^ (k << 8) ^ ((k & 1) << 4)] = v[k];
        __syncthreads();

        // ---- Exchange 1 load (CF) ----
#pragma unroll
        for (int j = 0; j < 16; j++)
            v[j] = sc[b1l ^ j];

        // ---- P2: H16 on e[0:4] ----
        h16(v);
        __syncthreads();

        // ---- Exchange 2 store (swz2, CF) ----
#pragma unroll
        for (int j = 0; j < 16; j++)
            sc[b2s ^ j] = v[j];
        __syncthreads();

        // ---- Exchange 2 load (CF) ----
#pragma unroll
        for (int r = 0; r < 16; r++)
            v[r] = sc[b2l ^ (r << 4) ^ ((r >> 1) & 7)];

        // ---- P3: H16 on e[4:8] ----
        h16(v);

        // ---- Store: e = (t&15) | r<<4 | (t>>4)<<8, scale 1/64.
        //      st.global.cs: evict-first, keep output stream out of L2's way.
        {
            const float c = 1.0f / 64.0f;
            float* yr = y + (size_t)row * FWHT_N + (t & 15) + ((t >> 4) << 8);
#pragma unroll
            for (int r = 0; r < 16; r++)
                __stcs(yr + (r << 4), v[r] * c);
        }

        cur ^= 1;
    }
}

extern "C" void kernel_launch(void* const* d_in, const int* in_sizes, int n_in,
                              void* d_out, int out_size) {
    const float* x = (const float*)d_in[0];
    float* y = (float*)d_out;
    const int rows = in_sizes[0] / FWHT_N;   // 8192
    const int grid = (rows < GRID) ? rows : GRID;
    fwht4096_kernel<<<grid, THREADS>>>(x, y, rows);
}